// round 15
// baseline (speedup 1.0000x reference)
#include <cuda_runtime.h>
#include <cuda_bf16.h>
#include <cuda_fp16.h>
#include <math.h>
#include <stdint.h>

#define D_MODEL 1024
#define N_HEADS 16
#define D_HEAD  64
#define B_SZ    4
#define T_SEQ   2048
#define M_ROWS  (B_SZ * T_SEQ)   // 8192

// ---------------- scratch (allocation-free rule: __device__ globals) --------
__device__ __half g_Qh[M_ROWS * D_MODEL];
__device__ __half g_Kh[M_ROWS * D_MODEL];
__device__ __half g_Vt[B_SZ * N_HEADS * D_HEAD * T_SEQ];   // [bh][dim][tok]
__device__ __nv_bfloat16 g_xhi[M_ROWS * D_MODEL];
__device__ __nv_bfloat16 g_xlo[M_ROWS * D_MODEL];
__device__ __nv_bfloat16 g_ohi[M_ROWS * D_MODEL];
__device__ __nv_bfloat16 g_olo[M_ROWS * D_MODEL];
__device__ __nv_bfloat16 g_whi[4 * D_MODEL * D_MODEL];
__device__ __nv_bfloat16 g_wlo[4 * D_MODEL * D_MODEL];

// ---------------- PTX helpers (all sm_80-compatible) ------------------------
__device__ __forceinline__ uint32_t smem_u32(const void* p) {
    uint32_t a;
    asm("{ .reg .u64 t; cvta.to.shared.u64 t, %1; cvt.u32.u64 %0, t; }" : "=r"(a) : "l"(p));
    return a;
}
__device__ __forceinline__ float ex2f(float x) {
    float y; asm("ex2.approx.f32 %0, %1;" : "=f"(y) : "f"(x)); return y;
}
__device__ __forceinline__ uint32_t f2h2(float a, float b) {
    __half2 h = __floats2half2_rn(a, b);
    return *reinterpret_cast<uint32_t*>(&h);
}
// fp16x2 exp2: one MUFU op for two values (P is fp16 anyway)
__device__ __forceinline__ uint32_t ex2h2(uint32_t x) {
    uint32_t y; asm("ex2.approx.f16x2 %0, %1;" : "=r"(y) : "r"(x)); return y;
}
__device__ __forceinline__ float2 h22f2(uint32_t x) {
    __half2 h = *reinterpret_cast<__half2*>(&x);
    return __half22float2(h);
}
__device__ __forceinline__ void mma16(float c[4], const uint32_t a[4], uint32_t b0, uint32_t b1) {
    asm("mma.sync.aligned.m16n8k16.row.col.f32.bf16.bf16.f32 "
        "{%0,%1,%2,%3}, {%4,%5,%6,%7}, {%8,%9}, {%0,%1,%2,%3};"
        : "+f"(c[0]), "+f"(c[1]), "+f"(c[2]), "+f"(c[3])
        : "r"(a[0]), "r"(a[1]), "r"(a[2]), "r"(a[3]), "r"(b0), "r"(b1));
}
__device__ __forceinline__ void mma16h(float c[4], const uint32_t a[4], uint32_t b0, uint32_t b1) {
    asm("mma.sync.aligned.m16n8k16.row.col.f32.f16.f16.f32 "
        "{%0,%1,%2,%3}, {%4,%5,%6,%7}, {%8,%9}, {%0,%1,%2,%3};"
        : "+f"(c[0]), "+f"(c[1]), "+f"(c[2]), "+f"(c[3])
        : "r"(a[0]), "r"(a[1]), "r"(a[2]), "r"(a[3]), "r"(b0), "r"(b1));
}
__device__ __forceinline__ void ldsm4(uint32_t addr, uint32_t r[4]) {
    asm volatile("ldmatrix.sync.aligned.m8n8.x4.shared.b16 {%0,%1,%2,%3}, [%4];"
        : "=r"(r[0]), "=r"(r[1]), "=r"(r[2]), "=r"(r[3]) : "r"(addr));
}
__device__ __forceinline__ void cp16(uint32_t saddr, const void* g) {
    asm volatile("cp.async.cg.shared.global [%0], [%1], 16;" :: "r"(saddr), "l"(g));
}
#define CP_COMMIT() asm volatile("cp.async.commit_group;" ::: "memory")
#define CP_WAIT1()  asm volatile("cp.async.wait_group 1;" ::: "memory")
#define CP_WAIT0()  asm volatile("cp.async.wait_group 0;" ::: "memory")

// ---------------------------------------------------------------------------
// Fused split: x + 4 weight matrices -> bf16 hi/lo, one launch. (R12-exact)
// ---------------------------------------------------------------------------
#define N4_X (M_ROWS * D_MODEL / 4)      // 2097152
#define N4_W (D_MODEL * D_MODEL / 4)     // 262144

__device__ __forceinline__ void split_store(const float* __restrict__ src,
                                            __nv_bfloat16* __restrict__ hi,
                                            __nv_bfloat16* __restrict__ lo, int i)
{
    float4 v = reinterpret_cast<const float4*>(src)[i];
    __nv_bfloat16 h0 = __float2bfloat16(v.x);
    __nv_bfloat16 h1 = __float2bfloat16(v.y);
    __nv_bfloat16 h2 = __float2bfloat16(v.z);
    __nv_bfloat16 h3 = __float2bfloat16(v.w);
    reinterpret_cast<__nv_bfloat162*>(hi)[2 * i]     = __halves2bfloat162(h0, h1);
    reinterpret_cast<__nv_bfloat162*>(hi)[2 * i + 1] = __halves2bfloat162(h2, h3);
    __nv_bfloat16 l0 = __float2bfloat16(v.x - __bfloat162float(h0));
    __nv_bfloat16 l1 = __float2bfloat16(v.y - __bfloat162float(h1));
    __nv_bfloat16 l2 = __float2bfloat16(v.z - __bfloat162float(h2));
    __nv_bfloat16 l3 = __float2bfloat16(v.w - __bfloat162float(h3));
    reinterpret_cast<__nv_bfloat162*>(lo)[2 * i]     = __halves2bfloat162(l0, l1);
    reinterpret_cast<__nv_bfloat162*>(lo)[2 * i + 1] = __halves2bfloat162(l2, l3);
}

__global__ void split_all(const float* __restrict__ x,
                          const float* __restrict__ Wq, const float* __restrict__ Wk,
                          const float* __restrict__ Wv, const float* __restrict__ Wo,
                          __nv_bfloat16* __restrict__ xhi, __nv_bfloat16* __restrict__ xlo,
                          __nv_bfloat16* __restrict__ whi, __nv_bfloat16* __restrict__ wlo)
{
    int i = blockIdx.x * blockDim.x + threadIdx.x;
    if (i < N4_X) {
        split_store(x, xhi, xlo, i);
    } else {
        int j = i - N4_X;
        int w = j >> 18;
        int o = j & (N4_W - 1);
        const float* src = (w == 0) ? Wq : (w == 1) ? Wk : (w == 2) ? Wv : Wo;
        size_t woff = (size_t)w * D_MODEL * D_MODEL;
        split_store(src, whi + woff, wlo + woff, o);
    }
}

// ---------------------------------------------------------------------------
// GEMM (R7-proven, 130us/launch): bf16x2 split (3 mma), fp32 acc.
// CTA 128x128, BK=32, 3-stage cp.async, 256 threads.
// ---------------------------------------------------------------------------
#define NSLAB 32
#define AHI_OFF 0
#define ALO_OFF 8192
#define BHI_OFF 16384
#define BLO_OFF 24576
#define STAGE_B 32768
#define G_SMEM (3 * STAGE_B)
#define QSCALE 0.18033688f            // (1/8) * log2(e)

__global__ __launch_bounds__(256, 2)
void gemm_bf16x2(const __nv_bfloat16* __restrict__ Ahi, const __nv_bfloat16* __restrict__ Alo,
                 const __nv_bfloat16* __restrict__ WhiB, const __nv_bfloat16* __restrict__ WloB,
                 const float* __restrict__ bias0, const float* __restrict__ bias1,
                 const float* __restrict__ bias2, int mode,
                 __half* __restrict__ Qh, __half* __restrict__ Kh, __half* __restrict__ Vt,
                 float* __restrict__ Co)
{
    extern __shared__ char smem[];
    const uint32_t sb = smem_u32(smem);
    const int tid = threadIdx.x, lane = tid & 31, warp = tid >> 5;
    const int g = lane >> 2, t = lane & 3;
    const int wm = warp >> 1, wn = warp & 1;
    const int m0 = blockIdx.y * 128, n0 = blockIdx.x * 128;
    const int z = blockIdx.z;

    const __nv_bfloat16* Bhi = WhiB + (size_t)z * D_MODEL * D_MODEL;
    const __nv_bfloat16* Blo = WloB + (size_t)z * D_MODEL * D_MODEL;
    const float* bias = (z == 0) ? bias0 : (z == 1) ? bias1 : bias2;

    auto load_slab = [&](int slab, int stage) {
        const uint32_t st = sb + stage * STAGE_B;
        const int kbyte = slab * 64;
#pragma unroll
        for (int i = 0; i < 2; i++) {
            int idx = tid + i * 256;
            int r = idx >> 2, c = idx & 3;
            uint32_t off = r * 64 + c * 16;
            uint32_t sw = off ^ ((off >> 3) & 0x30);
            size_t ga = (size_t)(m0 + r) * 2048 + kbyte + c * 16;
            cp16(st + AHI_OFF + sw, (const char*)Ahi + ga);
            cp16(st + ALO_OFF + sw, (const char*)Alo + ga);
            size_t gb = (size_t)(n0 + r) * 2048 + kbyte + c * 16;
            cp16(st + BHI_OFF + sw, (const char*)Bhi + gb);
            cp16(st + BLO_OFF + sw, (const char*)Blo + gb);
        }
    };

    float acc[2][8][4];
#pragma unroll
    for (int i = 0; i < 2; i++)
#pragma unroll
        for (int j = 0; j < 8; j++)
#pragma unroll
            for (int e = 0; e < 4; e++) acc[i][j][e] = 0.f;

    load_slab(0, 0); CP_COMMIT();
    load_slab(1, 1); CP_COMMIT();

    const int lr  = lane & 7;
    const int aR8 = ((lane >> 3) & 1) * 8;
    const int aCh = (lane >> 4);
    const int bR8 = (lane >> 4) * 8;
    const int bCh = (lane >> 3) & 1;

    for (int it = 0; it < NSLAB; it++) {
        const int s = it % 3;
        if (it == NSLAB - 1) { CP_WAIT0(); } else { CP_WAIT1(); }
        __syncthreads();

        const uint32_t stA_h = sb + s * STAGE_B + AHI_OFF;
        const uint32_t stA_l = sb + s * STAGE_B + ALO_OFF;
        const uint32_t stB_h = sb + s * STAGE_B + BHI_OFF;
        const uint32_t stB_l = sb + s * STAGE_B + BLO_OFF;

#pragma unroll
        for (int ks = 0; ks < 2; ks++) {
            uint32_t ah[2][4], al[2][4];
#pragma unroll
            for (int mt = 0; mt < 2; mt++) {
                int row = wm * 32 + mt * 16 + aR8 + lr;
                int ch  = ks * 2 + aCh;
                uint32_t off = row * 64 + ch * 16;
                uint32_t sw = off ^ ((off >> 3) & 0x30);
                ldsm4(stA_h + sw, ah[mt]);
                ldsm4(stA_l + sw, al[mt]);
            }
            uint32_t bh[4][4], bl[4][4];
#pragma unroll
            for (int np = 0; np < 4; np++) {
                int row = wn * 64 + np * 16 + bR8 + lr;
                int ch  = ks * 2 + bCh;
                uint32_t off = row * 64 + ch * 16;
                uint32_t sw = off ^ ((off >> 3) & 0x30);
                ldsm4(stB_h + sw, bh[np]);
                ldsm4(stB_l + sw, bl[np]);
            }
#pragma unroll
            for (int mt = 0; mt < 2; mt++) {
#pragma unroll
                for (int nf = 0; nf < 8; nf++) {
                    uint32_t b0h = bh[nf >> 1][(nf & 1) * 2];
                    uint32_t b1h = bh[nf >> 1][(nf & 1) * 2 + 1];
                    uint32_t b0l = bl[nf >> 1][(nf & 1) * 2];
                    uint32_t b1l = bl[nf >> 1][(nf & 1) * 2 + 1];
                    mma16(acc[mt][nf], ah[mt], b0h, b1h);
                    mma16(acc[mt][nf], ah[mt], b0l, b1l);
                    mma16(acc[mt][nf], al[mt], b0h, b1h);
                }
            }
        }
        if (it + 2 < NSLAB) { load_slab(it + 2, (it + 2) % 3); CP_COMMIT(); }
    }

#pragma unroll
    for (int mt = 0; mt < 2; mt++) {
#pragma unroll
        for (int nf = 0; nf < 8; nf++) {
            int col = n0 + wn * 64 + nf * 8 + 2 * t;
            float b0v = bias[col], b1v = bias[col + 1];
            int row0 = m0 + wm * 32 + mt * 16 + g;
            float v00 = acc[mt][nf][0] + b0v, v01 = acc[mt][nf][1] + b1v;
            float v10 = acc[mt][nf][2] + b0v, v11 = acc[mt][nf][3] + b1v;
            if (mode == 0) {
                *reinterpret_cast<float2*>(&Co[(size_t)row0 * D_MODEL + col]) = make_float2(v00, v01);
                *reinterpret_cast<float2*>(&Co[(size_t)(row0 + 8) * D_MODEL + col]) = make_float2(v10, v11);
            } else if (z == 0) {
                *reinterpret_cast<__half2*>(&Qh[(size_t)row0 * D_MODEL + col]) =
                    __floats2half2_rn(QSCALE * v00, QSCALE * v01);
                *reinterpret_cast<__half2*>(&Qh[(size_t)(row0 + 8) * D_MODEL + col]) =
                    __floats2half2_rn(QSCALE * v10, QSCALE * v11);
            } else if (z == 1) {
                *reinterpret_cast<__half2*>(&Kh[(size_t)row0 * D_MODEL + col]) =
                    __floats2half2_rn(v00, v01);
                *reinterpret_cast<__half2*>(&Kh[(size_t)(row0 + 8) * D_MODEL + col]) =
                    __floats2half2_rn(v10, v11);
            } else {
                int hh = col >> 6, dd = col & 63;
                int tok = row0 & 2047;
                size_t vbase = (size_t)((row0 >> 11) * 16 + hh) * 64;
                Vt[(vbase + dd) * T_SEQ + tok]         = __float2half(v00);
                Vt[(vbase + dd + 1) * T_SEQ + tok]     = __float2half(v01);
                Vt[(vbase + dd) * T_SEQ + tok + 8]     = __float2half(v10);
                Vt[(vbase + dd + 1) * T_SEQ + tok + 8] = __float2half(v11);
            }
        }
    }
}

// ---------------------------------------------------------------------------
// Flash attention v9: R14 math exactly (K-tile 64, register-P, fp16x2 exp),
// occupancy raised to 4 CTAs/SM (48KB smem x 4 = 192KB; 128 regs x 512 thr
// = full regfile). 16 independent warps/SM for latency hiding — no cross-
// warp coupling (unlike the failed R11 256-row block).
// ---------------------------------------------------------------------------
#define QS_OFF 0
#define KS_OFF 16384
#define VS_OFF 32768
#define FL_SMEM 49152

__global__ __launch_bounds__(128, 4)
void flash_h(const __half* __restrict__ Qh, const __half* __restrict__ Kh,
             const __half* __restrict__ Vt,
             __nv_bfloat16* __restrict__ Ohi, __nv_bfloat16* __restrict__ Olo)
{
    extern __shared__ char fsm[];
    const uint32_t sb = smem_u32(fsm);

    const int tid  = threadIdx.x;
    const int lane = tid & 31;
    const int warp = tid >> 5;
    const int g = lane >> 2, t = lane & 3;
    const int lr  = lane & 7;
    const int aR8 = ((lane >> 3) & 1) * 8;
    const int aCh = (lane >> 4);
    const int bR8 = (lane >> 4) * 8;
    const int bCh = (lane >> 3) & 1;

    const int qb = 15 - blockIdx.x;
    const int qstart = qb * 128;
    const int bh = blockIdx.y;
    const int b = bh >> 4;
    const int h = bh & 15;
    const int rowbase = b * T_SEQ;
    const int hoff = h * D_HEAD;

#pragma unroll
    for (int i = 0; i < 8; i++) {
        int idx = tid + i * 128;
        int r = idx >> 3, c = idx & 7;
        uint32_t off = r * 128 + c * 16;
        uint32_t sw = off ^ ((off >> 3) & 0x70);
        cp16(sb + QS_OFF + sw,
             (const char*)Qh + ((size_t)(rowbase + qstart + r) * D_MODEL + hoff) * 2 + c * 16);
    }
    auto prefetch = [&](int kt, int buf) {
#pragma unroll
        for (int i = 0; i < 4; i++) {
            int idx = tid + i * 128;
            int r = idx >> 3, c = idx & 7;
            uint32_t off = r * 128 + c * 16;
            uint32_t sw = off ^ ((off >> 3) & 0x70);
            cp16(sb + KS_OFF + buf * 8192 + sw,
                 (const char*)Kh + ((size_t)(rowbase + kt * 64 + r) * D_MODEL + hoff) * 2 + c * 16);
            cp16(sb + VS_OFF + buf * 8192 + sw,
                 (const char*)Vt + ((size_t)(bh * 64 + r) * T_SEQ + kt * 64) * 2 + c * 16);
        }
    };
    prefetch(0, 0);
    CP_COMMIT();
    CP_WAIT0();
    __syncthreads();

    uint32_t qa[2][4][4];
#pragma unroll
    for (int mt = 0; mt < 2; mt++)
#pragma unroll
        for (int kc = 0; kc < 4; kc++) {
            uint32_t off = (uint32_t)(warp * 32 + mt * 16 + aR8 + lr) * 128 + (kc * 2 + aCh) * 16;
            uint32_t sw = off ^ ((off >> 3) & 0x70);
            ldsm4(sb + QS_OFF + sw, qa[mt][kc]);
        }

    float o[2][8][4];
#pragma unroll
    for (int mt = 0; mt < 2; mt++)
#pragma unroll
        for (int nf = 0; nf < 8; nf++)
#pragma unroll
            for (int e = 0; e < 4; e++) o[mt][nf][e] = 0.f;
    float mr[2][2], lsum[2][2];
#pragma unroll
    for (int mt = 0; mt < 2; mt++) {
        mr[mt][0] = -INFINITY; mr[mt][1] = -INFINITY;
        lsum[mt][0] = 0.f; lsum[mt][1] = 0.f;
    }

    const int ktmax = 2 * qb + 1;
    for (int kt = 0; kt <= ktmax; kt++) {
        const int kb = kt * 64;
        const int buf = kt & 1;
        const uint32_t ksb = sb + KS_OFF + buf * 8192;
        const uint32_t vsb = sb + VS_OFF + buf * 8192;

        if (kt < ktmax) { prefetch(kt + 1, buf ^ 1); CP_COMMIT(); }

        float s[2][8][4];
#pragma unroll
        for (int mt = 0; mt < 2; mt++)
#pragma unroll
            for (int nf = 0; nf < 8; nf++)
#pragma unroll
                for (int e = 0; e < 4; e++) s[mt][nf][e] = 0.f;

#pragma unroll
        for (int kc = 0; kc < 4; kc++) {
            uint32_t kbf[4][4];
#pragma unroll
            for (int np = 0; np < 4; np++) {
                uint32_t off = (uint32_t)(np * 16 + bR8 + lr) * 128 + (kc * 2 + bCh) * 16;
                uint32_t sw = off ^ ((off >> 3) & 0x70);
                ldsm4(ksb + sw, kbf[np]);
            }
#pragma unroll
            for (int nf = 0; nf < 8; nf++) {
                uint32_t b0 = kbf[nf >> 1][(nf & 1) * 2];
                uint32_t b1 = kbf[nf >> 1][(nf & 1) * 2 + 1];
                mma16h(s[0][nf], qa[0][kc], b0, b1);
                mma16h(s[1][nf], qa[1][kc], b0, b1);
            }
        }

        if (kt >= 2 * qb) {
#pragma unroll
            for (int mt = 0; mt < 2; mt++) {
                int rb = qstart + warp * 32 + mt * 16 + g;
#pragma unroll
                for (int nf = 0; nf < 8; nf++) {
                    int c0 = kb + nf * 8 + 2 * t;
                    if (c0     > rb)     s[mt][nf][0] = -INFINITY;
                    if (c0 + 1 > rb)     s[mt][nf][1] = -INFINITY;
                    if (c0     > rb + 8) s[mt][nf][2] = -INFINITY;
                    if (c0 + 1 > rb + 8) s[mt][nf][3] = -INFINITY;
                }
            }
        }

        // ---- softmax with fp16x2 exp; P stays packed for the P@V mma ----
        uint32_t ph[2][8][2];
#pragma unroll
        for (int mt = 0; mt < 2; mt++) {
            float mx0 = -INFINITY, mx1 = -INFINITY;
#pragma unroll
            for (int nf = 0; nf < 8; nf++) {
                mx0 = fmaxf(mx0, fmaxf(s[mt][nf][0], s[mt][nf][1]));
                mx1 = fmaxf(mx1, fmaxf(s[mt][nf][2], s[mt][nf][3]));
            }
            mx0 = fmaxf(mx0, __shfl_xor_sync(0xffffffffu, mx0, 1));
            mx0 = fmaxf(mx0, __shfl_xor_sync(0xffffffffu, mx0, 2));
            mx1 = fmaxf(mx1, __shfl_xor_sync(0xffffffffu, mx1, 1));
            mx1 = fmaxf(mx1, __shfl_xor_sync(0xffffffffu, mx1, 2));

            float mn0 = fmaxf(mr[mt][0], mx0), mn1 = fmaxf(mr[mt][1], mx1);
            float corr0 = ex2f(mr[mt][0] - mn0), corr1 = ex2f(mr[mt][1] - mn1);
            float sum0 = 0.f, sum1 = 0.f;
#pragma unroll
            for (int nf = 0; nf < 8; nf++) {
                uint32_t p01 = ex2h2(f2h2(s[mt][nf][0] - mn0, s[mt][nf][1] - mn0));
                uint32_t p23 = ex2h2(f2h2(s[mt][nf][2] - mn1, s[mt][nf][3] - mn1));
                ph[mt][nf][0] = p01;
                ph[mt][nf][1] = p23;
                float2 f01 = h22f2(p01);
                float2 f23 = h22f2(p23);
                sum0 += f01.x + f01.y;
                sum1 += f23.x + f23.y;
            }
            sum0 += __shfl_xor_sync(0xffffffffu, sum0, 1);
            sum0 += __shfl_xor_sync(0xffffffffu, sum0, 2);
            sum1 += __shfl_xor_sync(0xffffffffu, sum1, 1);
            sum1 += __shfl_xor_sync(0xffffffffu, sum1, 2);

            lsum[mt][0] = lsum[mt][0] * corr0 + sum0;  mr[mt][0] = mn0;
            lsum[mt][1] = lsum[mt][1] * corr1 + sum1;  mr[mt][1] = mn1;
#pragma unroll
            for (int nf = 0; nf < 8; nf++) {
                o[mt][nf][0] *= corr0; o[mt][nf][1] *= corr0;
                o[mt][nf][2] *= corr1; o[mt][nf][3] *= corr1;
            }
        }

        // ---- O += P @ V : P A-fragments are the packed ph registers ----
#pragma unroll
        for (int kc = 0; kc < 4; kc++) {
            uint32_t paf[2][4];
#pragma unroll
            for (int mt = 0; mt < 2; mt++) {
                paf[mt][0] = ph[mt][2 * kc][0];
                paf[mt][1] = ph[mt][2 * kc][1];
                paf[mt][2] = ph[mt][2 * kc + 1][0];
                paf[mt][3] = ph[mt][2 * kc + 1][1];
            }
            uint32_t vbf[4][4];
#pragma unroll
            for (int np = 0; np < 4; np++) {
                uint32_t off = (uint32_t)(np * 16 + bR8 + lr) * 128 + (kc * 2 + bCh) * 16;
                uint32_t sw = off ^ ((off >> 3) & 0x70);
                ldsm4(vsb + sw, vbf[np]);
            }
#pragma unroll
            for (int nf = 0; nf < 8; nf++) {
                uint32_t b0 = vbf[nf >> 1][(nf & 1) * 2];
                uint32_t b1 = vbf[nf >> 1][(nf & 1) * 2 + 1];
                mma16h(o[0][nf], paf[0], b0, b1);
                mma16h(o[1][nf], paf[1], b0, b1);
            }
        }

        if (kt < ktmax) CP_WAIT0();
        __syncthreads();
    }

#pragma unroll
    for (int mt = 0; mt < 2; mt++) {
        float inv0 = 1.0f / lsum[mt][0], inv1 = 1.0f / lsum[mt][1];
        int ro0 = rowbase + qstart + warp * 32 + mt * 16 + g;
#pragma unroll
        for (int nf = 0; nf < 8; nf++) {
            int colx = hoff + nf * 8 + 2 * t;
            float v00 = o[mt][nf][0] * inv0, v01 = o[mt][nf][1] * inv0;
            float v10 = o[mt][nf][2] * inv1, v11 = o[mt][nf][3] * inv1;
            __nv_bfloat16 h00 = __float2bfloat16(v00), h01 = __float2bfloat16(v01);
            __nv_bfloat16 h10 = __float2bfloat16(v10), h11 = __float2bfloat16(v11);
            *reinterpret_cast<__nv_bfloat162*>(&Ohi[(size_t)ro0 * D_MODEL + colx]) =
                __halves2bfloat162(h00, h01);
            *reinterpret_cast<__nv_bfloat162*>(&Ohi[(size_t)(ro0 + 8) * D_MODEL + colx]) =
                __halves2bfloat162(h10, h11);
            __nv_bfloat16 l00 = __float2bfloat16(v00 - __bfloat162float(h00));
            __nv_bfloat16 l01 = __float2bfloat16(v01 - __bfloat162float(h01));
            __nv_bfloat16 l10 = __float2bfloat16(v10 - __bfloat162float(h10));
            __nv_bfloat16 l11 = __float2bfloat16(v11 - __bfloat162float(h11));
            *reinterpret_cast<__nv_bfloat162*>(&Olo[(size_t)ro0 * D_MODEL + colx]) =
                __halves2bfloat162(l00, l01);
            *reinterpret_cast<__nv_bfloat162*>(&Olo[(size_t)(ro0 + 8) * D_MODEL + colx]) =
                __halves2bfloat162(l10, l11);
        }
    }
}

// ---------------------------------------------------------------------------
// Launch
// ---------------------------------------------------------------------------
extern "C" void kernel_launch(void* const* d_in, const int* in_sizes, int n_in,
                              void* d_out, int out_size)
{
    const float* x  = (const float*)d_in[0];
    const float* Wq = (const float*)d_in[1];
    const float* bq = (const float*)d_in[2];
    const float* Wk = (const float*)d_in[3];
    const float* bk = (const float*)d_in[4];
    const float* Wv = (const float*)d_in[5];
    const float* bv = (const float*)d_in[6];
    const float* Wo = (const float*)d_in[7];
    const float* bo = (const float*)d_in[8];
    float* out = (float*)d_out;

    __half *Qh, *Kh, *Vt;
    __nv_bfloat16 *xhi, *xlo, *ohi, *olo, *whi, *wlo;
    cudaGetSymbolAddress((void**)&Qh, g_Qh);
    cudaGetSymbolAddress((void**)&Kh, g_Kh);
    cudaGetSymbolAddress((void**)&Vt, g_Vt);
    cudaGetSymbolAddress((void**)&xhi, g_xhi);
    cudaGetSymbolAddress((void**)&xlo, g_xlo);
    cudaGetSymbolAddress((void**)&ohi, g_ohi);
    cudaGetSymbolAddress((void**)&olo, g_olo);
    cudaGetSymbolAddress((void**)&whi, g_whi);
    cudaGetSymbolAddress((void**)&wlo, g_wlo);

    cudaFuncSetAttribute(gemm_bf16x2, cudaFuncAttributeMaxDynamicSharedMemorySize, G_SMEM);
    cudaFuncSetAttribute(flash_h, cudaFuncAttributeMaxDynamicSharedMemorySize, FL_SMEM);

    const size_t wstep = (size_t)D_MODEL * D_MODEL;
    const int n4total = N4_X + 4 * N4_W;

    split_all<<<n4total / 256, 256>>>(x, Wq, Wk, Wv, Wo, xhi, xlo, whi, wlo);

    dim3 qkvgrid(D_MODEL / 128, M_ROWS / 128, 3);
    gemm_bf16x2<<<qkvgrid, 256, G_SMEM>>>(xhi, xlo, whi, wlo, bq, bk, bv,
                                          1, Qh, Kh, Vt, nullptr);

    dim3 fgrid(T_SEQ / 128, B_SZ * N_HEADS);
    flash_h<<<fgrid, 128, FL_SMEM>>>(Qh, Kh, Vt, ohi, olo);

    dim3 ogrid(D_MODEL / 128, M_ROWS / 128, 1);
    gemm_bf16x2<<<ogrid, 256, G_SMEM>>>(ohi, olo, whi + 3 * wstep, wlo + 3 * wstep,
                                        bo, bo, bo, 0, nullptr, nullptr, nullptr, out);
}

// round 16
// speedup vs baseline: 1.3088x; 1.3088x over previous
#include <cuda_runtime.h>
#include <cuda_bf16.h>
#include <cuda_fp16.h>
#include <math.h>
#include <stdint.h>

#define D_MODEL 1024
#define N_HEADS 16
#define D_HEAD  64
#define B_SZ    4
#define T_SEQ   2048
#define M_ROWS  (B_SZ * T_SEQ)   // 8192

// ---------------- scratch (allocation-free rule: __device__ globals) --------
__device__ __half g_Qh[M_ROWS * D_MODEL];
__device__ __half g_Kh[M_ROWS * D_MODEL];
__device__ __half g_Vt[B_SZ * N_HEADS * D_HEAD * T_SEQ];   // [bh][dim][tok]
__device__ __nv_bfloat16 g_xhi[M_ROWS * D_MODEL];
__device__ __nv_bfloat16 g_xlo[M_ROWS * D_MODEL];
__device__ __nv_bfloat16 g_ohi[M_ROWS * D_MODEL];
__device__ __nv_bfloat16 g_olo[M_ROWS * D_MODEL];
__device__ __nv_bfloat16 g_whi[4 * D_MODEL * D_MODEL];
__device__ __nv_bfloat16 g_wlo[4 * D_MODEL * D_MODEL];

// ---------------- PTX helpers (all sm_80-compatible) ------------------------
__device__ __forceinline__ uint32_t smem_u32(const void* p) {
    uint32_t a;
    asm("{ .reg .u64 t; cvta.to.shared.u64 t, %1; cvt.u32.u64 %0, t; }" : "=r"(a) : "l"(p));
    return a;
}
__device__ __forceinline__ float ex2f(float x) {
    float y; asm("ex2.approx.f32 %0, %1;" : "=f"(y) : "f"(x)); return y;
}
__device__ __forceinline__ uint32_t f2h2(float a, float b) {
    __half2 h = __floats2half2_rn(a, b);
    return *reinterpret_cast<uint32_t*>(&h);
}
// fp16x2 exp2: one MUFU op for two values (P is fp16 anyway)
__device__ __forceinline__ uint32_t ex2h2(uint32_t x) {
    uint32_t y; asm("ex2.approx.f16x2 %0, %1;" : "=r"(y) : "r"(x)); return y;
}
__device__ __forceinline__ float2 h22f2(uint32_t x) {
    __half2 h = *reinterpret_cast<__half2*>(&x);
    return __half22float2(h);
}
__device__ __forceinline__ void mma16(float c[4], const uint32_t a[4], uint32_t b0, uint32_t b1) {
    asm("mma.sync.aligned.m16n8k16.row.col.f32.bf16.bf16.f32 "
        "{%0,%1,%2,%3}, {%4,%5,%6,%7}, {%8,%9}, {%0,%1,%2,%3};"
        : "+f"(c[0]), "+f"(c[1]), "+f"(c[2]), "+f"(c[3])
        : "r"(a[0]), "r"(a[1]), "r"(a[2]), "r"(a[3]), "r"(b0), "r"(b1));
}
__device__ __forceinline__ void mma16h(float c[4], const uint32_t a[4], uint32_t b0, uint32_t b1) {
    asm("mma.sync.aligned.m16n8k16.row.col.f32.f16.f16.f32 "
        "{%0,%1,%2,%3}, {%4,%5,%6,%7}, {%8,%9}, {%0,%1,%2,%3};"
        : "+f"(c[0]), "+f"(c[1]), "+f"(c[2]), "+f"(c[3])
        : "r"(a[0]), "r"(a[1]), "r"(a[2]), "r"(a[3]), "r"(b0), "r"(b1));
}
__device__ __forceinline__ void ldsm4(uint32_t addr, uint32_t r[4]) {
    asm volatile("ldmatrix.sync.aligned.m8n8.x4.shared.b16 {%0,%1,%2,%3}, [%4];"
        : "=r"(r[0]), "=r"(r[1]), "=r"(r[2]), "=r"(r[3]) : "r"(addr));
}
__device__ __forceinline__ void cp16(uint32_t saddr, const void* g) {
    asm volatile("cp.async.cg.shared.global [%0], [%1], 16;" :: "r"(saddr), "l"(g));
}
#define CP_COMMIT() asm volatile("cp.async.commit_group;" ::: "memory")
#define CP_WAIT1()  asm volatile("cp.async.wait_group 1;" ::: "memory")
#define CP_WAIT0()  asm volatile("cp.async.wait_group 0;" ::: "memory")

// ---------------------------------------------------------------------------
// Fused split: x + 4 weight matrices -> bf16 hi/lo, one launch.
// ---------------------------------------------------------------------------
#define N4_X (M_ROWS * D_MODEL / 4)      // 2097152
#define N4_W (D_MODEL * D_MODEL / 4)     // 262144

__device__ __forceinline__ void split_store(const float* __restrict__ src,
                                            __nv_bfloat16* __restrict__ hi,
                                            __nv_bfloat16* __restrict__ lo, int i)
{
    float4 v = reinterpret_cast<const float4*>(src)[i];
    __nv_bfloat16 h0 = __float2bfloat16(v.x);
    __nv_bfloat16 h1 = __float2bfloat16(v.y);
    __nv_bfloat16 h2 = __float2bfloat16(v.z);
    __nv_bfloat16 h3 = __float2bfloat16(v.w);
    reinterpret_cast<__nv_bfloat162*>(hi)[2 * i]     = __halves2bfloat162(h0, h1);
    reinterpret_cast<__nv_bfloat162*>(hi)[2 * i + 1] = __halves2bfloat162(h2, h3);
    __nv_bfloat16 l0 = __float2bfloat16(v.x - __bfloat162float(h0));
    __nv_bfloat16 l1 = __float2bfloat16(v.y - __bfloat162float(h1));
    __nv_bfloat16 l2 = __float2bfloat16(v.z - __bfloat162float(h2));
    __nv_bfloat16 l3 = __float2bfloat16(v.w - __bfloat162float(h3));
    reinterpret_cast<__nv_bfloat162*>(lo)[2 * i]     = __halves2bfloat162(l0, l1);
    reinterpret_cast<__nv_bfloat162*>(lo)[2 * i + 1] = __halves2bfloat162(l2, l3);
}

__global__ void split_all(const float* __restrict__ x,
                          const float* __restrict__ Wq, const float* __restrict__ Wk,
                          const float* __restrict__ Wv, const float* __restrict__ Wo,
                          __nv_bfloat16* __restrict__ xhi, __nv_bfloat16* __restrict__ xlo,
                          __nv_bfloat16* __restrict__ whi, __nv_bfloat16* __restrict__ wlo)
{
    int i = blockIdx.x * blockDim.x + threadIdx.x;
    if (i < N4_X) {
        split_store(x, xhi, xlo, i);
    } else {
        int j = i - N4_X;
        int w = j >> 18;
        int o = j & (N4_W - 1);
        const float* src = (w == 0) ? Wq : (w == 1) ? Wk : (w == 2) ? Wv : Wo;
        size_t woff = (size_t)w * D_MODEL * D_MODEL;
        split_store(src, whi + woff, wlo + woff, o);
    }
}

// ---------------------------------------------------------------------------
// GEMM (R7-proven, 130us/launch): bf16x2 split (3 mma), fp32 acc.
// CTA 128x128, BK=32, 3-stage cp.async, 256 threads.
// ---------------------------------------------------------------------------
#define NSLAB 32
#define AHI_OFF 0
#define ALO_OFF 8192
#define BHI_OFF 16384
#define BLO_OFF 24576
#define STAGE_B 32768
#define G_SMEM (3 * STAGE_B)
#define QSCALE 0.18033688f            // (1/8) * log2(e)

__global__ __launch_bounds__(256, 2)
void gemm_bf16x2(const __nv_bfloat16* __restrict__ Ahi, const __nv_bfloat16* __restrict__ Alo,
                 const __nv_bfloat16* __restrict__ WhiB, const __nv_bfloat16* __restrict__ WloB,
                 const float* __restrict__ bias0, const float* __restrict__ bias1,
                 const float* __restrict__ bias2, int mode,
                 __half* __restrict__ Qh, __half* __restrict__ Kh, __half* __restrict__ Vt,
                 float* __restrict__ Co)
{
    extern __shared__ char smem[];
    const uint32_t sb = smem_u32(smem);
    const int tid = threadIdx.x, lane = tid & 31, warp = tid >> 5;
    const int g = lane >> 2, t = lane & 3;
    const int wm = warp >> 1, wn = warp & 1;
    const int m0 = blockIdx.y * 128, n0 = blockIdx.x * 128;
    const int z = blockIdx.z;

    const __nv_bfloat16* Bhi = WhiB + (size_t)z * D_MODEL * D_MODEL;
    const __nv_bfloat16* Blo = WloB + (size_t)z * D_MODEL * D_MODEL;
    const float* bias = (z == 0) ? bias0 : (z == 1) ? bias1 : bias2;

    auto load_slab = [&](int slab, int stage) {
        const uint32_t st = sb + stage * STAGE_B;
        const int kbyte = slab * 64;
#pragma unroll
        for (int i = 0; i < 2; i++) {
            int idx = tid + i * 256;
            int r = idx >> 2, c = idx & 3;
            uint32_t off = r * 64 + c * 16;
            uint32_t sw = off ^ ((off >> 3) & 0x30);
            size_t ga = (size_t)(m0 + r) * 2048 + kbyte + c * 16;
            cp16(st + AHI_OFF + sw, (const char*)Ahi + ga);
            cp16(st + ALO_OFF + sw, (const char*)Alo + ga);
            size_t gb = (size_t)(n0 + r) * 2048 + kbyte + c * 16;
            cp16(st + BHI_OFF + sw, (const char*)Bhi + gb);
            cp16(st + BLO_OFF + sw, (const char*)Blo + gb);
        }
    };

    float acc[2][8][4];
#pragma unroll
    for (int i = 0; i < 2; i++)
#pragma unroll
        for (int j = 0; j < 8; j++)
#pragma unroll
            for (int e = 0; e < 4; e++) acc[i][j][e] = 0.f;

    load_slab(0, 0); CP_COMMIT();
    load_slab(1, 1); CP_COMMIT();

    const int lr  = lane & 7;
    const int aR8 = ((lane >> 3) & 1) * 8;
    const int aCh = (lane >> 4);
    const int bR8 = (lane >> 4) * 8;
    const int bCh = (lane >> 3) & 1;

    for (int it = 0; it < NSLAB; it++) {
        const int s = it % 3;
        if (it == NSLAB - 1) { CP_WAIT0(); } else { CP_WAIT1(); }
        __syncthreads();

        const uint32_t stA_h = sb + s * STAGE_B + AHI_OFF;
        const uint32_t stA_l = sb + s * STAGE_B + ALO_OFF;
        const uint32_t stB_h = sb + s * STAGE_B + BHI_OFF;
        const uint32_t stB_l = sb + s * STAGE_B + BLO_OFF;

#pragma unroll
        for (int ks = 0; ks < 2; ks++) {
            uint32_t ah[2][4], al[2][4];
#pragma unroll
            for (int mt = 0; mt < 2; mt++) {
                int row = wm * 32 + mt * 16 + aR8 + lr;
                int ch  = ks * 2 + aCh;
                uint32_t off = row * 64 + ch * 16;
                uint32_t sw = off ^ ((off >> 3) & 0x30);
                ldsm4(stA_h + sw, ah[mt]);
                ldsm4(stA_l + sw, al[mt]);
            }
            uint32_t bh[4][4], bl[4][4];
#pragma unroll
            for (int np = 0; np < 4; np++) {
                int row = wn * 64 + np * 16 + bR8 + lr;
                int ch  = ks * 2 + bCh;
                uint32_t off = row * 64 + ch * 16;
                uint32_t sw = off ^ ((off >> 3) & 0x30);
                ldsm4(stB_h + sw, bh[np]);
                ldsm4(stB_l + sw, bl[np]);
            }
#pragma unroll
            for (int mt = 0; mt < 2; mt++) {
#pragma unroll
                for (int nf = 0; nf < 8; nf++) {
                    uint32_t b0h = bh[nf >> 1][(nf & 1) * 2];
                    uint32_t b1h = bh[nf >> 1][(nf & 1) * 2 + 1];
                    uint32_t b0l = bl[nf >> 1][(nf & 1) * 2];
                    uint32_t b1l = bl[nf >> 1][(nf & 1) * 2 + 1];
                    mma16(acc[mt][nf], ah[mt], b0h, b1h);
                    mma16(acc[mt][nf], ah[mt], b0l, b1l);
                    mma16(acc[mt][nf], al[mt], b0h, b1h);
                }
            }
        }
        if (it + 2 < NSLAB) { load_slab(it + 2, (it + 2) % 3); CP_COMMIT(); }
    }

#pragma unroll
    for (int mt = 0; mt < 2; mt++) {
#pragma unroll
        for (int nf = 0; nf < 8; nf++) {
            int col = n0 + wn * 64 + nf * 8 + 2 * t;
            float b0v = bias[col], b1v = bias[col + 1];
            int row0 = m0 + wm * 32 + mt * 16 + g;
            float v00 = acc[mt][nf][0] + b0v, v01 = acc[mt][nf][1] + b1v;
            float v10 = acc[mt][nf][2] + b0v, v11 = acc[mt][nf][3] + b1v;
            if (mode == 0) {
                *reinterpret_cast<float2*>(&Co[(size_t)row0 * D_MODEL + col]) = make_float2(v00, v01);
                *reinterpret_cast<float2*>(&Co[(size_t)(row0 + 8) * D_MODEL + col]) = make_float2(v10, v11);
            } else if (z == 0) {
                *reinterpret_cast<__half2*>(&Qh[(size_t)row0 * D_MODEL + col]) =
                    __floats2half2_rn(QSCALE * v00, QSCALE * v01);
                *reinterpret_cast<__half2*>(&Qh[(size_t)(row0 + 8) * D_MODEL + col]) =
                    __floats2half2_rn(QSCALE * v10, QSCALE * v11);
            } else if (z == 1) {
                *reinterpret_cast<__half2*>(&Kh[(size_t)row0 * D_MODEL + col]) =
                    __floats2half2_rn(v00, v01);
                *reinterpret_cast<__half2*>(&Kh[(size_t)(row0 + 8) * D_MODEL + col]) =
                    __floats2half2_rn(v10, v11);
            } else {
                int hh = col >> 6, dd = col & 63;
                int tok = row0 & 2047;
                size_t vbase = (size_t)((row0 >> 11) * 16 + hh) * 64;
                Vt[(vbase + dd) * T_SEQ + tok]         = __float2half(v00);
                Vt[(vbase + dd + 1) * T_SEQ + tok]     = __float2half(v01);
                Vt[(vbase + dd) * T_SEQ + tok + 8]     = __float2half(v10);
                Vt[(vbase + dd + 1) * T_SEQ + tok + 8] = __float2half(v11);
            }
        }
    }
}

// ---------------------------------------------------------------------------
// Flash attention v8 (R14-proven best): K-tile 64, register-P, fp16x2 exp.
// 4 warps, 2 CTAs/SM (register footprint forbids more — R9/R11/R15).
// smem: Q 16K | K 2x8K | V 2x8K = 48KB.
// ---------------------------------------------------------------------------
#define QS_OFF 0
#define KS_OFF 16384
#define VS_OFF 32768
#define FL_SMEM 49152

__global__ __launch_bounds__(128, 2)
void flash_h(const __half* __restrict__ Qh, const __half* __restrict__ Kh,
             const __half* __restrict__ Vt,
             __nv_bfloat16* __restrict__ Ohi, __nv_bfloat16* __restrict__ Olo)
{
    extern __shared__ char fsm[];
    const uint32_t sb = smem_u32(fsm);

    const int tid  = threadIdx.x;
    const int lane = tid & 31;
    const int warp = tid >> 5;
    const int g = lane >> 2, t = lane & 3;
    const int lr  = lane & 7;
    const int aR8 = ((lane >> 3) & 1) * 8;
    const int aCh = (lane >> 4);
    const int bR8 = (lane >> 4) * 8;
    const int bCh = (lane >> 3) & 1;

    const int qb = 15 - blockIdx.x;
    const int qstart = qb * 128;
    const int bh = blockIdx.y;
    const int b = bh >> 4;
    const int h = bh & 15;
    const int rowbase = b * T_SEQ;
    const int hoff = h * D_HEAD;

#pragma unroll
    for (int i = 0; i < 8; i++) {
        int idx = tid + i * 128;
        int r = idx >> 3, c = idx & 7;
        uint32_t off = r * 128 + c * 16;
        uint32_t sw = off ^ ((off >> 3) & 0x70);
        cp16(sb + QS_OFF + sw,
             (const char*)Qh + ((size_t)(rowbase + qstart + r) * D_MODEL + hoff) * 2 + c * 16);
    }
    auto prefetch = [&](int kt, int buf) {
#pragma unroll
        for (int i = 0; i < 4; i++) {
            int idx = tid + i * 128;
            int r = idx >> 3, c = idx & 7;
            uint32_t off = r * 128 + c * 16;
            uint32_t sw = off ^ ((off >> 3) & 0x70);
            cp16(sb + KS_OFF + buf * 8192 + sw,
                 (const char*)Kh + ((size_t)(rowbase + kt * 64 + r) * D_MODEL + hoff) * 2 + c * 16);
            cp16(sb + VS_OFF + buf * 8192 + sw,
                 (const char*)Vt + ((size_t)(bh * 64 + r) * T_SEQ + kt * 64) * 2 + c * 16);
        }
    };
    prefetch(0, 0);
    CP_COMMIT();
    CP_WAIT0();
    __syncthreads();

    uint32_t qa[2][4][4];
#pragma unroll
    for (int mt = 0; mt < 2; mt++)
#pragma unroll
        for (int kc = 0; kc < 4; kc++) {
            uint32_t off = (uint32_t)(warp * 32 + mt * 16 + aR8 + lr) * 128 + (kc * 2 + aCh) * 16;
            uint32_t sw = off ^ ((off >> 3) & 0x70);
            ldsm4(sb + QS_OFF + sw, qa[mt][kc]);
        }

    float o[2][8][4];
#pragma unroll
    for (int mt = 0; mt < 2; mt++)
#pragma unroll
        for (int nf = 0; nf < 8; nf++)
#pragma unroll
            for (int e = 0; e < 4; e++) o[mt][nf][e] = 0.f;
    float mr[2][2], lsum[2][2];
#pragma unroll
    for (int mt = 0; mt < 2; mt++) {
        mr[mt][0] = -INFINITY; mr[mt][1] = -INFINITY;
        lsum[mt][0] = 0.f; lsum[mt][1] = 0.f;
    }

    const int ktmax = 2 * qb + 1;
    for (int kt = 0; kt <= ktmax; kt++) {
        const int kb = kt * 64;
        const int buf = kt & 1;
        const uint32_t ksb = sb + KS_OFF + buf * 8192;
        const uint32_t vsb = sb + VS_OFF + buf * 8192;

        if (kt < ktmax) { prefetch(kt + 1, buf ^ 1); CP_COMMIT(); }

        float s[2][8][4];
#pragma unroll
        for (int mt = 0; mt < 2; mt++)
#pragma unroll
            for (int nf = 0; nf < 8; nf++)
#pragma unroll
                for (int e = 0; e < 4; e++) s[mt][nf][e] = 0.f;

#pragma unroll
        for (int kc = 0; kc < 4; kc++) {
            uint32_t kbf[4][4];
#pragma unroll
            for (int np = 0; np < 4; np++) {
                uint32_t off = (uint32_t)(np * 16 + bR8 + lr) * 128 + (kc * 2 + bCh) * 16;
                uint32_t sw = off ^ ((off >> 3) & 0x70);
                ldsm4(ksb + sw, kbf[np]);
            }
#pragma unroll
            for (int nf = 0; nf < 8; nf++) {
                uint32_t b0 = kbf[nf >> 1][(nf & 1) * 2];
                uint32_t b1 = kbf[nf >> 1][(nf & 1) * 2 + 1];
                mma16h(s[0][nf], qa[0][kc], b0, b1);
                mma16h(s[1][nf], qa[1][kc], b0, b1);
            }
        }

        if (kt >= 2 * qb) {
#pragma unroll
            for (int mt = 0; mt < 2; mt++) {
                int rb = qstart + warp * 32 + mt * 16 + g;
#pragma unroll
                for (int nf = 0; nf < 8; nf++) {
                    int c0 = kb + nf * 8 + 2 * t;
                    if (c0     > rb)     s[mt][nf][0] = -INFINITY;
                    if (c0 + 1 > rb)     s[mt][nf][1] = -INFINITY;
                    if (c0     > rb + 8) s[mt][nf][2] = -INFINITY;
                    if (c0 + 1 > rb + 8) s[mt][nf][3] = -INFINITY;
                }
            }
        }

        // ---- softmax with fp16x2 exp; P stays packed for the P@V mma ----
        uint32_t ph[2][8][2];
#pragma unroll
        for (int mt = 0; mt < 2; mt++) {
            float mx0 = -INFINITY, mx1 = -INFINITY;
#pragma unroll
            for (int nf = 0; nf < 8; nf++) {
                mx0 = fmaxf(mx0, fmaxf(s[mt][nf][0], s[mt][nf][1]));
                mx1 = fmaxf(mx1, fmaxf(s[mt][nf][2], s[mt][nf][3]));
            }
            mx0 = fmaxf(mx0, __shfl_xor_sync(0xffffffffu, mx0, 1));
            mx0 = fmaxf(mx0, __shfl_xor_sync(0xffffffffu, mx0, 2));
            mx1 = fmaxf(mx1, __shfl_xor_sync(0xffffffffu, mx1, 1));
            mx1 = fmaxf(mx1, __shfl_xor_sync(0xffffffffu, mx1, 2));

            float mn0 = fmaxf(mr[mt][0], mx0), mn1 = fmaxf(mr[mt][1], mx1);
            float corr0 = ex2f(mr[mt][0] - mn0), corr1 = ex2f(mr[mt][1] - mn1);
            float sum0 = 0.f, sum1 = 0.f;
#pragma unroll
            for (int nf = 0; nf < 8; nf++) {
                uint32_t p01 = ex2h2(f2h2(s[mt][nf][0] - mn0, s[mt][nf][1] - mn0));
                uint32_t p23 = ex2h2(f2h2(s[mt][nf][2] - mn1, s[mt][nf][3] - mn1));
                ph[mt][nf][0] = p01;
                ph[mt][nf][1] = p23;
                float2 f01 = h22f2(p01);
                float2 f23 = h22f2(p23);
                sum0 += f01.x + f01.y;
                sum1 += f23.x + f23.y;
            }
            sum0 += __shfl_xor_sync(0xffffffffu, sum0, 1);
            sum0 += __shfl_xor_sync(0xffffffffu, sum0, 2);
            sum1 += __shfl_xor_sync(0xffffffffu, sum1, 1);
            sum1 += __shfl_xor_sync(0xffffffffu, sum1, 2);

            lsum[mt][0] = lsum[mt][0] * corr0 + sum0;  mr[mt][0] = mn0;
            lsum[mt][1] = lsum[mt][1] * corr1 + sum1;  mr[mt][1] = mn1;
#pragma unroll
            for (int nf = 0; nf < 8; nf++) {
                o[mt][nf][0] *= corr0; o[mt][nf][1] *= corr0;
                o[mt][nf][2] *= corr1; o[mt][nf][3] *= corr1;
            }
        }

        // ---- O += P @ V : P A-fragments are the packed ph registers ----
#pragma unroll
        for (int kc = 0; kc < 4; kc++) {
            uint32_t paf[2][4];
#pragma unroll
            for (int mt = 0; mt < 2; mt++) {
                paf[mt][0] = ph[mt][2 * kc][0];
                paf[mt][1] = ph[mt][2 * kc][1];
                paf[mt][2] = ph[mt][2 * kc + 1][0];
                paf[mt][3] = ph[mt][2 * kc + 1][1];
            }
            uint32_t vbf[4][4];
#pragma unroll
            for (int np = 0; np < 4; np++) {
                uint32_t off = (uint32_t)(np * 16 + bR8 + lr) * 128 + (kc * 2 + bCh) * 16;
                uint32_t sw = off ^ ((off >> 3) & 0x70);
                ldsm4(vsb + sw, vbf[np]);
            }
#pragma unroll
            for (int nf = 0; nf < 8; nf++) {
                uint32_t b0 = vbf[nf >> 1][(nf & 1) * 2];
                uint32_t b1 = vbf[nf >> 1][(nf & 1) * 2 + 1];
                mma16h(o[0][nf], paf[0], b0, b1);
                mma16h(o[1][nf], paf[1], b0, b1);
            }
        }

        if (kt < ktmax) CP_WAIT0();
        __syncthreads();
    }

#pragma unroll
    for (int mt = 0; mt < 2; mt++) {
        float inv0 = 1.0f / lsum[mt][0], inv1 = 1.0f / lsum[mt][1];
        int ro0 = rowbase + qstart + warp * 32 + mt * 16 + g;
#pragma unroll
        for (int nf = 0; nf < 8; nf++) {
            int colx = hoff + nf * 8 + 2 * t;
            float v00 = o[mt][nf][0] * inv0, v01 = o[mt][nf][1] * inv0;
            float v10 = o[mt][nf][2] * inv1, v11 = o[mt][nf][3] * inv1;
            __nv_bfloat16 h00 = __float2bfloat16(v00), h01 = __float2bfloat16(v01);
            __nv_bfloat16 h10 = __float2bfloat16(v10), h11 = __float2bfloat16(v11);
            *reinterpret_cast<__nv_bfloat162*>(&Ohi[(size_t)ro0 * D_MODEL + colx]) =
                __halves2bfloat162(h00, h01);
            *reinterpret_cast<__nv_bfloat162*>(&Ohi[(size_t)(ro0 + 8) * D_MODEL + colx]) =
                __halves2bfloat162(h10, h11);
            __nv_bfloat16 l00 = __float2bfloat16(v00 - __bfloat162float(h00));
            __nv_bfloat16 l01 = __float2bfloat16(v01 - __bfloat162float(h01));
            __nv_bfloat16 l10 = __float2bfloat16(v10 - __bfloat162float(h10));
            __nv_bfloat16 l11 = __float2bfloat16(v11 - __bfloat162float(h11));
            *reinterpret_cast<__nv_bfloat162*>(&Olo[(size_t)ro0 * D_MODEL + colx]) =
                __halves2bfloat162(l00, l01);
            *reinterpret_cast<__nv_bfloat162*>(&Olo[(size_t)(ro0 + 8) * D_MODEL + colx]) =
                __halves2bfloat162(l10, l11);
        }
    }
}

// ---------------------------------------------------------------------------
// Launch
// ---------------------------------------------------------------------------
extern "C" void kernel_launch(void* const* d_in, const int* in_sizes, int n_in,
                              void* d_out, int out_size)
{
    const float* x  = (const float*)d_in[0];
    const float* Wq = (const float*)d_in[1];
    const float* bq = (const float*)d_in[2];
    const float* Wk = (const float*)d_in[3];
    const float* bk = (const float*)d_in[4];
    const float* Wv = (const float*)d_in[5];
    const float* bv = (const float*)d_in[6];
    const float* Wo = (const float*)d_in[7];
    const float* bo = (const float*)d_in[8];
    float* out = (float*)d_out;

    __half *Qh, *Kh, *Vt;
    __nv_bfloat16 *xhi, *xlo, *ohi, *olo, *whi, *wlo;
    cudaGetSymbolAddress((void**)&Qh, g_Qh);
    cudaGetSymbolAddress((void**)&Kh, g_Kh);
    cudaGetSymbolAddress((void**)&Vt, g_Vt);
    cudaGetSymbolAddress((void**)&xhi, g_xhi);
    cudaGetSymbolAddress((void**)&xlo, g_xlo);
    cudaGetSymbolAddress((void**)&ohi, g_ohi);
    cudaGetSymbolAddress((void**)&olo, g_olo);
    cudaGetSymbolAddress((void**)&whi, g_whi);
    cudaGetSymbolAddress((void**)&wlo, g_wlo);

    cudaFuncSetAttribute(gemm_bf16x2, cudaFuncAttributeMaxDynamicSharedMemorySize, G_SMEM);
    cudaFuncSetAttribute(flash_h, cudaFuncAttributeMaxDynamicSharedMemorySize, FL_SMEM);

    const size_t wstep = (size_t)D_MODEL * D_MODEL;
    const int n4total = N4_X + 4 * N4_W;

    split_all<<<n4total / 256, 256>>>(x, Wq, Wk, Wv, Wo, xhi, xlo, whi, wlo);

    dim3 qkvgrid(D_MODEL / 128, M_ROWS / 128, 3);
    gemm_bf16x2<<<qkvgrid, 256, G_SMEM>>>(xhi, xlo, whi, wlo, bq, bk, bv,
                                          1, Qh, Kh, Vt, nullptr);

    dim3 fgrid(T_SEQ / 128, B_SZ * N_HEADS);
    flash_h<<<fgrid, 128, FL_SMEM>>>(Qh, Kh, Vt, ohi, olo);

    dim3 ogrid(D_MODEL / 128, M_ROWS / 128, 1);
    gemm_bf16x2<<<ogrid, 256, G_SMEM>>>(ohi, olo, whi + 3 * wstep, wlo + 3 * wstep,
                                        bo, bo, bo, 0, nullptr, nullptr, nullptr, out);
}